// round 16
// baseline (speedup 1.0000x reference)
#include <cuda_runtime.h>
#include <cuda_bf16.h>
#include <math.h>
#include <stdint.h>

// ---------------- problem constants ----------------
#define Bc 2
#define Sc 2048
#define Ec 1024
#define Hc 16
#define HDc 64
#define DFFc 4096
#define Mc (Bc*Sc)          // 4096 tokens
#define NM 6                // Wq Wk Wv Wo W1 W2
#define ROUTE_THR 0.05f

// ---------------- device scratch (no allocations allowed) ----------------
__device__ __nv_bfloat16 g_whQKV[3*Ec*Ec];
__device__ __nv_bfloat16 g_wlQKV[3*Ec*Ec];
__device__ __nv_bfloat16 g_whO[Ec*Ec];
__device__ __nv_bfloat16 g_wlO[Ec*Ec];
__device__ __nv_bfloat16 g_wh1[DFFc*Ec];
__device__ __nv_bfloat16 g_wl1[DFFc*Ec];
__device__ __nv_bfloat16 g_wh2[Ec*DFFc];
__device__ __nv_bfloat16 g_wl2[Ec*DFFc];
__device__ float g_biasQKV[3*Ec];

__device__ __nv_bfloat16 g_xh[Mc*Ec];
__device__ __nv_bfloat16 g_xl[Mc*Ec];
__device__ __nv_bfloat16 g_qkvh[Mc*3*Ec];
__device__ __nv_bfloat16 g_qkvl[Mc*3*Ec];
__device__ __nv_bfloat16 g_atth[Mc*Ec];
__device__ __nv_bfloat16 g_attl[Mc*Ec];
__device__ float g_oout[Mc*Ec];
__device__ float g_x1[Mc*Ec];
__device__ __nv_bfloat16 g_x1h[Mc*Ec];
__device__ __nv_bfloat16 g_x1l[Mc*Ec];
__device__ __nv_bfloat16 g_ffh[Mc*DFFc];
__device__ __nv_bfloat16 g_ffl[Mc*DFFc];
__device__ float g_f2[Mc*Ec];

// selection state
struct SelSt {
    unsigned long long rk, rk1;
    unsigned pref, pref1;
    unsigned val, val1;
};
__device__ SelSt    g_sel[2][NM];
__device__ unsigned g_hist[2][3][NM][2][2048];
__device__ unsigned g_cnt[2][3][NM];
__device__ unsigned g_cntAl[NM];
__device__ float    g_thr[NM], g_alpha[NM], g_rthr[NM];
__device__ double   g_aSum[NM];
__device__ unsigned long long g_aCnt[NM];

struct PP { const float* W[NM]; int N[NM]; };
struct Ranks { long long kA[NM]; double fA[NM]; long long kB[NM]; double fB[NM]; };
struct WSplit { __nv_bfloat16* hi[NM]; __nv_bfloat16* lo[NM]; };

// ---------------- init / zero ----------------
__global__ void init_k(Ranks r) {
    int t = blockIdx.x*blockDim.x + threadIdx.x;
    int total = 2*3*NM*2*2048;
    unsigned* h = &g_hist[0][0][0][0][0];
    for (int i = t; i < total; i += gridDim.x*blockDim.x) h[i] = 0u;
    if (t < 2*3*NM) (&g_cnt[0][0][0])[t] = 0u;
    if (t < NM) {
        g_cntAl[t] = 0u;
        SelSt s0; s0.rk = (unsigned long long)r.kA[t]; s0.rk1 = s0.rk + 1ULL;
        s0.pref = 0; s0.pref1 = 0; s0.val = 0; s0.val1 = 0;
        g_sel[0][t] = s0;
        SelSt s1; s1.rk = (unsigned long long)r.kB[t]; s1.rk1 = s1.rk + 1ULL;
        s1.pref = 0; s1.pref1 = 0; s1.val = 0; s1.val1 = 0;
        g_sel[1][t] = s1;
        g_aSum[t] = 0.0; g_aCnt[t] = 0ULL;
    }
}

// ---------------- histogram passes (MLP=4, fused last-block scan) ---------
template<int STAGE, int LEVEL>
__global__ __launch_bounds__(256) void hist_k(PP pp, Ranks rkk) {
    __shared__ unsigned h0[2048];
    __shared__ unsigned h1[2048];
    __shared__ bool isLast;
    int m = blockIdx.y;
    int N4 = pp.N[m] >> 2;
    const float4* __restrict__ W = (const float4*)pp.W[m];
    for (int i = threadIdx.x; i < 2048; i += blockDim.x) { h0[i]=0u; h1[i]=0u; }
    unsigned p0=0, p1=0;
    if (LEVEL > 0) { p0 = g_sel[STAGE][m].pref; p1 = g_sel[STAGE][m].pref1; }
    float thr=0.f, alpha=0.f;
    if (STAGE==1) { thr = g_thr[m]; alpha = g_alpha[m]; }
    __syncthreads();
    unsigned* rep = ((threadIdx.x >> 5) & 1) ? h1 : h0;

    auto proc = [&](float4 w4) {
        float wv[4] = {w4.x, w4.y, w4.z, w4.w};
        #pragma unroll
        for (int u = 0; u < 4; u++) {
            float w = wv[u];
            float a = fabsf(w);
            unsigned bits;
            if (STAGE==0) bits = __float_as_uint(a);
            else {
                float wq = (a > thr) ? copysignf(alpha, w) : 0.0f;
                bits = __float_as_uint(fabsf(w - wq));
            }
            if (LEVEL==0) {
                atomicAdd(&rep[bits>>21], 1u);
            } else if (LEVEL==1) {
                if ((bits>>21)==p0) atomicAdd(&h0[(bits>>10)&2047u], 1u);
                if ((bits>>21)==p1) atomicAdd(&h1[(bits>>10)&2047u], 1u);
            } else {
                if ((bits>>10)==p0) atomicAdd(&h0[bits&1023u], 1u);
                if ((bits>>10)==p1) atomicAdd(&h1[bits&1023u], 1u);
            }
        }
    };

    int stride = gridDim.x*blockDim.x;
    int i = blockIdx.x*blockDim.x + threadIdx.x;
    for (; i + 3*stride < N4; i += 4*stride) {
        float4 q0 = W[i], q1 = W[i+stride], q2 = W[i+2*stride], q3 = W[i+3*stride];
        proc(q0); proc(q1); proc(q2); proc(q3);
    }
    for (; i < N4; i += stride) proc(W[i]);

    __syncthreads();
    const int nb = (LEVEL==2) ? 1024 : 2048;
    if (LEVEL==0) {
        for (int j = threadIdx.x; j < 2048; j += blockDim.x) {
            unsigned v = h0[j] + h1[j];
            if (v) atomicAdd(&g_hist[STAGE][LEVEL][m][0][j], v);
        }
    } else {
        for (int j = threadIdx.x; j < nb; j += blockDim.x) {
            if (h0[j]) atomicAdd(&g_hist[STAGE][LEVEL][m][0][j], h0[j]);
            if (h1[j]) atomicAdd(&g_hist[STAGE][LEVEL][m][1][j], h1[j]);
        }
    }
    __threadfence();
    __syncthreads();
    if (threadIdx.x == 0) {
        unsigned done = atomicAdd(&g_cnt[STAGE][LEVEL][m], 1u);
        isLast = (done == gridDim.x - 1);
    }
    __syncthreads();
    if (!isLast) return;

    volatile unsigned* gh0 = g_hist[STAGE][LEVEL][m][0];
    volatile unsigned* gh1 = g_hist[STAGE][LEVEL][m][1];
    for (int j = threadIdx.x; j < nb; j += blockDim.x) {
        unsigned a = gh0[j];
        h0[j] = a;
        h1[j] = (LEVEL==0) ? a : gh1[j];
    }
    __syncthreads();
    if (threadIdx.x < 2) {
        int which = threadIdx.x;
        SelSt s = g_sel[STAGE][m];
        unsigned long long rank = which ? s.rk1 : s.rk;
        unsigned pref = which ? s.pref1 : s.pref;
        unsigned long long c = 0;
        int bsel = 0;
        unsigned* hh = which ? h1 : h0;
        for (int b = 0; b < nb; b++) {
            c += hh[b];
            if (c > rank) { bsel = b; rank -= (c - hh[b]); break; }
        }
        if (LEVEL==0)      pref = (unsigned)bsel;
        else if (LEVEL==1) pref = (pref<<11) | (unsigned)bsel;
        else {
            unsigned val = (pref<<10) | (unsigned)bsel;
            if (which) g_sel[STAGE][m].val1 = val; else g_sel[STAGE][m].val = val;
        }
        if (LEVEL < 2) {
            if (which) { g_sel[STAGE][m].pref1 = pref; g_sel[STAGE][m].rk1 = rank; }
            else       { g_sel[STAGE][m].pref  = pref; g_sel[STAGE][m].rk  = rank; }
        }
    }
    if (LEVEL==2) {
        __syncthreads();
        if (threadIdx.x==0) {
            double a0 = (double)__uint_as_float(g_sel[STAGE][m].val);
            double a1 = (double)__uint_as_float(g_sel[STAGE][m].val1);
            double f  = (STAGE==1) ? rkk.fB[m] : rkk.fA[m];
            float t = (float)(a0 + f*(a1-a0));
            if (STAGE==0) g_thr[m] = t; else g_rthr[m] = t;
        }
    }
}

// ---------------- alpha (MLP=4, fused finalize) ----------------
__global__ __launch_bounds__(256) void alpha_k(PP pp) {
    int m = blockIdx.y;
    int N4 = pp.N[m] >> 2;
    const float4* __restrict__ W = (const float4*)pp.W[m];
    float thr = g_thr[m];
    double s = 0.0; unsigned long long c = 0ULL;

    auto proc = [&](float4 w4) {
        float av[4] = {fabsf(w4.x), fabsf(w4.y), fabsf(w4.z), fabsf(w4.w)};
        #pragma unroll
        for (int u = 0; u < 4; u++)
            if (av[u] > thr) { s += (double)av[u]; c++; }
    };
    int stride = gridDim.x*blockDim.x;
    int i = blockIdx.x*blockDim.x + threadIdx.x;
    for (; i + 3*stride < N4; i += 4*stride) {
        float4 q0 = W[i], q1 = W[i+stride], q2 = W[i+2*stride], q3 = W[i+3*stride];
        proc(q0); proc(q1); proc(q2); proc(q3);
    }
    for (; i < N4; i += stride) proc(W[i]);

    __shared__ double sd[256];
    __shared__ unsigned long long sc[256];
    __shared__ bool isLastA;
    int tid = threadIdx.x;
    sd[tid] = s; sc[tid] = c;
    __syncthreads();
    for (int off = 128; off > 0; off >>= 1) {
        if (tid < off) { sd[tid] += sd[tid+off]; sc[tid] += sc[tid+off]; }
        __syncthreads();
    }
    if (tid==0) {
        atomicAdd(&g_aSum[m], sd[0]);
        atomicAdd(&g_aCnt[m], sc[0]);
    }
    __threadfence();
    __syncthreads();
    if (tid==0) {
        unsigned done = atomicAdd(&g_cntAl[m], 1u);
        isLastA = (done == gridDim.x - 1);
    }
    __syncthreads();
    if (isLastA && tid==0) {
        double ssum = *((volatile double*)&g_aSum[m]);
        unsigned long long cc = *((volatile unsigned long long*)&g_aCnt[m]);
        double cd = (double)cc; if (cd < 1.0) cd = 1.0;
        g_alpha[m] = (float)(ssum/cd);
    }
}

// ---------------- effective weight write: split bf16 hi/lo (MLP=4) ----------
__global__ __launch_bounds__(256) void weff_k(PP pp, WSplit ws) {
    int m = blockIdx.y;
    int N4 = pp.N[m] >> 2;
    const float4* __restrict__ W = (const float4*)pp.W[m];
    __nv_bfloat16* __restrict__ OH = ws.hi[m];
    __nv_bfloat16* __restrict__ OL = ws.lo[m];
    float thr = g_thr[m], alpha = g_alpha[m], rthr = g_rthr[m];

    auto proc = [&](float4 w4, int idx4) {
        float wv[4] = {w4.x, w4.y, w4.z, w4.w};
        __nv_bfloat16 hb[4], lb[4];
        #pragma unroll
        for (int u = 0; u < 4; u++) {
            float w = wv[u];
            float a = fabsf(w);
            float wq = (a > thr) ? copysignf(alpha, w) : 0.0f;
            float rr = w - wq;
            float o = wq + ((fabsf(rr) >= rthr) ? rr : 0.0f);
            hb[u] = __float2bfloat16(o);
            lb[u] = __float2bfloat16(o - __bfloat162float(hb[u]));
        }
        int off = idx4*4;
        *(__nv_bfloat162*)(OH+off)   = __halves2bfloat162(hb[0], hb[1]);
        *(__nv_bfloat162*)(OH+off+2) = __halves2bfloat162(hb[2], hb[3]);
        *(__nv_bfloat162*)(OL+off)   = __halves2bfloat162(lb[0], lb[1]);
        *(__nv_bfloat162*)(OL+off+2) = __halves2bfloat162(lb[2], lb[3]);
    };
    int stride = gridDim.x*blockDim.x;
    int i = blockIdx.x*blockDim.x + threadIdx.x;
    for (; i + 3*stride < N4; i += 4*stride) {
        float4 q0 = W[i], q1 = W[i+stride], q2 = W[i+2*stride], q3 = W[i+3*stride];
        proc(q0, i); proc(q1, i+stride); proc(q2, i+2*stride); proc(q3, i+3*stride);
    }
    for (; i < N4; i += stride) proc(W[i], i);
}

__global__ void concat_bias_k(const float* __restrict__ bq, const float* __restrict__ bk,
                              const float* __restrict__ bv, float* __restrict__ out) {
    int i = blockIdx.x*blockDim.x + threadIdx.x;
    if (i < Ec) { out[i] = bq[i]; out[Ec+i] = bk[i]; out[2*Ec+i] = bv[i]; }
}

// ---------------- split fp32 -> bf16 hi/lo ----------------
__global__ __launch_bounds__(256) void split_k(const float4* __restrict__ X,
                                               __nv_bfloat16* __restrict__ H,
                                               __nv_bfloat16* __restrict__ L,
                                               int n4) {
    int i = blockIdx.x*blockDim.x + threadIdx.x;
    if (i >= n4) return;
    float4 v = X[i];
    float f[4] = {v.x, v.y, v.z, v.w};
    __nv_bfloat16 hb[4], lb[4];
    #pragma unroll
    for (int u=0;u<4;u++) {
        hb[u] = __float2bfloat16(f[u]);
        lb[u] = __float2bfloat16(f[u] - __bfloat162float(hb[u]));
    }
    int off = i*4;
    *(__nv_bfloat162*)(H+off)   = __halves2bfloat162(hb[0], hb[1]);
    *(__nv_bfloat162*)(H+off+2) = __halves2bfloat162(hb[2], hb[3]);
    *(__nv_bfloat162*)(L+off)   = __halves2bfloat162(lb[0], lb[1]);
    *(__nv_bfloat162*)(L+off+2) = __halves2bfloat162(lb[2], lb[3]);
}

// ---------------- tensor-core helpers ----------------
__device__ __forceinline__ float gelu_exact(float v) {
    return 0.5f*v*(1.0f + erff(v*0.70710678118654752440f));
}

__device__ __forceinline__ void ldmx4(uint32_t* r, const __nv_bfloat16* p) {
    unsigned a = (unsigned)__cvta_generic_to_shared(p);
    asm volatile("ldmatrix.sync.aligned.m8n8.x4.shared.b16 {%0,%1,%2,%3}, [%4];"
        : "=r"(r[0]), "=r"(r[1]), "=r"(r[2]), "=r"(r[3]) : "r"(a));
}

__device__ __forceinline__ void mma_bf16(float* c, const uint32_t* a, const uint32_t* b) {
    asm volatile("mma.sync.aligned.m16n8k16.row.col.f32.bf16.bf16.f32 "
        "{%0,%1,%2,%3}, {%4,%5,%6,%7}, {%8,%9}, {%0,%1,%2,%3};"
        : "+f"(c[0]), "+f"(c[1]), "+f"(c[2]), "+f"(c[3])
        : "r"(a[0]), "r"(a[1]), "r"(a[2]), "r"(a[3]), "r"(b[0]), "r"(b[1]));
}

__device__ __forceinline__ void cpasync16(__nv_bfloat16* dst, const __nv_bfloat16* src) {
    unsigned d = (unsigned)__cvta_generic_to_shared(dst);
    asm volatile("cp.async.ca.shared.global [%0], [%1], 16;" :: "r"(d), "l"(src));
}

// ---------------- tensor-core GEMM (pre-split operands, 2-stage cp.async) --
#define TBM 128
#define TBN 128
#define TBK 32
#define LDT 40
#define TILE_E (TBM*LDT)

template<int EPI>   // 0=none(fp32) 2=gelu(bf16 split out) 3=route(bf16 split out)
__global__ __launch_bounds__(256) void gemm_tc(const __nv_bfloat16* __restrict__ AH,
                                               const __nv_bfloat16* __restrict__ AL,
                                               const __nv_bfloat16* __restrict__ BH,
                                               const __nv_bfloat16* __restrict__ BL,
                                               const float* __restrict__ bias,
                                               float* __restrict__ Cf,
                                               __nv_bfloat16* __restrict__ CH,
                                               __nv_bfloat16* __restrict__ CL,
                                               int M, int N, int K) {
    extern __shared__ __nv_bfloat16 sh[];
    const int m0 = blockIdx.y*TBM, n0 = blockIdx.x*TBN;
    const int tid = threadIdx.x;
    const int lane = tid & 31;
    const int wid = tid >> 5;
    const int wm = (wid >> 2) * 64;
    const int wn = (wid & 3) * 32;

    float acc[4][4][4];
    #pragma unroll
    for (int i=0;i<4;i++)
        #pragma unroll
        for (int j=0;j<4;j++)
            #pragma unroll
            for (int r=0;r<4;r++) acc[i][j][r] = 0.f;

    const __nv_bfloat16* base0 = AH + (size_t)m0*K;
    const __nv_bfloat16* base1 = AL + (size_t)m0*K;
    const __nv_bfloat16* base2 = BH + (size_t)n0*K;
    const __nv_bfloat16* base3 = BL + (size_t)n0*K;

    auto issue = [&](int ch, int s) {
        int k0 = ch*TBK;
        __nv_bfloat16* dst = sh + s*4*TILE_E;
        #pragma unroll
        for (int j = 0; j < 8; j++) {
            const int arr = j >> 1;
            int e = tid + (j & 1)*256;
            int r = e >> 2, c = (e & 3) * 8;
            const __nv_bfloat16* src =
                (arr==0 ? base0 : arr==1 ? base1 : arr==2 ? base2 : base3)
                + (size_t)r*K + k0 + c;
            cpasync16(dst + arr*TILE_E + r*LDT + c, src);
        }
    };

    const int nch = K / TBK;
    issue(0, 0);
    asm volatile("cp.async.commit_group;");

    for (int ch = 0; ch < nch; ch++) {
        const int cur = ch & 1;
        if (ch + 1 < nch) {
            issue(ch+1, cur^1);
            asm volatile("cp.async.commit_group;");
            asm volatile("cp.async.wait_group 1;");
        } else {
            asm volatile("cp.async.wait_group 0;");
        }
        __syncthreads();

        const __nv_bfloat16* Ah = sh + cur*4*TILE_E;
        const __nv_bfloat16* Al = Ah + TILE_E;
        const __nv_bfloat16* Bh = Ah + 2*TILE_E;
        const __nv_bfloat16* Bl = Ah + 3*TILE_E;

        #pragma unroll
        for (int kk = 0; kk < TBK; kk += 16) {
            uint32_t ah[4][4], al[4][4], bh[4][2], bl[4][2];
            int arow = (lane & 15);
            int acol = kk + (lane >> 4) * 8;
            #pragma unroll
            for (int tm = 0; tm < 4; tm++) {
                int r = wm + tm*16 + arow;
                ldmx4(ah[tm], Ah + r*LDT + acol);
                ldmx4(al[tm], Al + r*LDT + acol);
            }
            int brow = ((lane >> 4) << 3) + (lane & 7);
            int bcol = kk + ((lane >> 3) & 1) * 8;
            #pragma unroll
            for (int g = 0; g < 2; g++) {
                uint32_t t[4];
                int r = wn + g*16 + brow;
                ldmx4(t, Bh + r*LDT + bcol);
                bh[2*g][0]=t[0]; bh[2*g][1]=t[1]; bh[2*g+1][0]=t[2]; bh[2*g+1][1]=t[3];
                ldmx4(t, Bl + r*LDT + bcol);
                bl[2*g][0]=t[0]; bl[2*g][1]=t[1]; bl[2*g+1][0]=t[2]; bl[2*g+1][1]=t[3];
            }
            #pragma unroll
            for (int tm = 0; tm < 4; tm++)
                #pragma unroll
                for (int tn = 0; tn < 4; tn++) {
                    mma_bf16(acc[tm][tn], ah[tm], bh[tn]);
                    mma_bf16(acc[tm][tn], ah[tm], bl[tn]);
                    mma_bf16(acc[tm][tn], al[tm], bh[tn]);
                }
        }
        __syncthreads();
    }

    #pragma unroll
    for (int tm = 0; tm < 4; tm++) {
        #pragma unroll
        for (int tn = 0; tn < 4; tn++) {
            int row = m0 + wm + tm*16 + (lane >> 2);
            int col = n0 + wn + tn*8 + (lane & 3)*2;
            float b0 = bias[col], b1 = bias[col+1];
            float v0 = acc[tm][tn][0] + b0;
            float v1 = acc[tm][tn][1] + b1;
            float v2 = acc[tm][tn][2] + b0;
            float v3 = acc[tm][tn][3] + b1;
            if (EPI==3) {
                v0 = (fabsf(v0) > ROUTE_THR) ? v0 : 0.0f;
                v1 = (fabsf(v1) > ROUTE_THR) ? v1 : 0.0f;
                v2 = (fabsf(v2) > ROUTE_THR) ? v2 : 0.0f;
                v3 = (fabsf(v3) > ROUTE_THR) ? v3 : 0.0f;
            }
            if (EPI==2) {
                v0 = gelu_exact(v0); v1 = gelu_exact(v1);
                v2 = gelu_exact(v2); v3 = gelu_exact(v3);
            }
            if (EPI==2 || EPI==3) {
                __nv_bfloat16 h0 = __float2bfloat16(v0), h1 = __float2bfloat16(v1);
                __nv_bfloat16 h2 = __float2bfloat16(v2), h3 = __float2bfloat16(v3);
                __nv_bfloat16 l0 = __float2bfloat16(v0 - __bfloat162float(h0));
                __nv_bfloat16 l1 = __float2bfloat16(v1 - __bfloat162float(h1));
                __nv_bfloat16 l2 = __float2bfloat16(v2 - __bfloat162float(h2));
                __nv_bfloat16 l3 = __float2bfloat16(v3 - __bfloat162float(h3));
                *(__nv_bfloat162*)(CH + (size_t)row*N + col)     = __halves2bfloat162(h0, h1);
                *(__nv_bfloat162*)(CH + (size_t)(row+8)*N + col) = __halves2bfloat162(h2, h3);
                *(__nv_bfloat162*)(CL + (size_t)row*N + col)     = __halves2bfloat162(l0, l1);
                *(__nv_bfloat162*)(CL + (size_t)(row+8)*N + col) = __halves2bfloat162(l2, l3);
            } else {
                *(float2*)(Cf + (size_t)row*N + col)     = make_float2(v0, v1);
                *(float2*)(Cf + (size_t)(row+8)*N + col) = make_float2(v2, v3);
            }
        }
    }
}

// ---------------- tensor-core flash attention (split QKV inputs) ----------
#define AQ 128
#define AK 128
#define SQK 72
#define SVP 136
#define ATTN_SMEM_BYTES ((2*AQ*SQK + 2*AK*SQK + 2*HDc*SVP + 2*AQ*SVP)*2 + (AQ+AQ+4*AQ)*4 + AK*4)

__global__ __launch_bounds__(256) void attn_tc(const __nv_bfloat16* __restrict__ QKVH,
                                               const __nv_bfloat16* __restrict__ QKVL,
                                               const int* __restrict__ mask,
                                               __nv_bfloat16* __restrict__ OgH,
                                               __nv_bfloat16* __restrict__ OgL) {
    extern __shared__ __nv_bfloat16 sb[];
    __nv_bfloat16* Qh  = sb;
    __nv_bfloat16* Ql  = Qh  + AQ*SQK;
    __nv_bfloat16* Kh  = Ql  + AQ*SQK;
    __nv_bfloat16* Kl  = Kh  + AK*SQK;
    __nv_bfloat16* Vth = Kl  + AK*SQK;
    __nv_bfloat16* Vtl = Vth + HDc*SVP;
    __nv_bfloat16* Ph  = Vtl + HDc*SVP;
    __nv_bfloat16* Pl  = Ph  + AQ*SVP;
    float* mrow = (float*)(Pl + AQ*SVP);
    float* lrow = mrow + AQ;
    float* red  = lrow + AQ;
    int*   mcol = (int*)(red + 4*AQ);

    const int tid = threadIdx.x, lane = tid & 31, wid = tid >> 5;
    const int b = blockIdx.z, h = blockIdx.y, q0 = blockIdx.x*AQ;
    const int E3 = 3*Ec;
    const __nv_bfloat16* QgH = QKVH + ((size_t)b*Sc + q0)*E3 + h*HDc;
    const __nv_bfloat16* QgL = QKVL + ((size_t)b*Sc + q0)*E3 + h*HDc;
    const __nv_bfloat16* KgH = QKVH + (size_t)b*Sc*E3 + Ec + h*HDc;
    const __nv_bfloat16* KgL = QKVL + (size_t)b*Sc*E3 + Ec + h*HDc;
    const __nv_bfloat16* VgH = QKVH + (size_t)b*Sc*E3 + 2*Ec + h*HDc;
    const __nv_bfloat16* VgL = QKVL + (size_t)b*Sc*E3 + 2*Ec + h*HDc;

    for (int i = tid; i < AQ*8; i += 256) {
        int r = i >> 3, c = (i & 7) * 8;
        cpasync16(Qh + r*SQK + c, QgH + (size_t)r*E3 + c);
        cpasync16(Ql + r*SQK + c, QgL + (size_t)r*E3 + c);
    }
    if (tid < AQ) { mrow[tid] = -INFINITY; lrow[tid] = 0.f; }

    const int wm = (wid >> 2) * 64;
    const int wn = (wid & 3) * 32;
    const int wd = (wid & 3) * 16;
    const int wq = wid & 3;

    float o[4][2][4];
    #pragma unroll
    for (int i=0;i<4;i++)
        #pragma unroll
        for (int j=0;j<2;j++)
            #pragma unroll
            for (int r=0;r<4;r++) o[i][j][r] = 0.f;

    for (int t = 0; t < Sc/AK; t++) {
        __syncthreads();
        for (int i = tid; i < AK*8; i += 256) {
            int r = i >> 3, c = (i & 7) * 8;
            size_t g = (size_t)(t*AK + r)*E3 + c;
            cpasync16(Kh + r*SQK + c, KgH + g);
            cpasync16(Kl + r*SQK + c, KgL + g);
        }
        asm volatile("cp.async.commit_group;");
        for (int i = tid; i < AK*8; i += 256) {
            int r = i >> 3, c = (i & 7) * 8;
            size_t g = (size_t)(t*AK + r)*E3 + c;
            uint4 vh4 = *(const uint4*)(VgH + g);
            uint4 vl4 = *(const uint4*)(VgL + g);
            const __nv_bfloat16* hs = (const __nv_bfloat16*)&vh4;
            const __nv_bfloat16* ls = (const __nv_bfloat16*)&vl4;
            #pragma unroll
            for (int u=0;u<8;u++) {
                Vth[(c+u)*SVP + r] = hs[u];
                Vtl[(c+u)*SVP + r] = ls[u];
            }
        }
        if (tid < AK) mcol[tid] = mask[b*Sc + t*AK + tid];
        asm volatile("cp.async.wait_group 0;");
        __syncthreads();

        float s[4][4][4];
        #pragma unroll
        for (int i=0;i<4;i++)
            #pragma unroll
            for (int j=0;j<4;j++)
                #pragma unroll
                for (int r=0;r<4;r++) s[i][j][r] = 0.f;

        #pragma unroll
        for (int kk = 0; kk < HDc; kk += 16) {
            uint32_t ah[4][4], al[4][4], bh[4][2], bl[4][2];
            int arow = (lane & 15);
            int acol = kk + (lane >> 4) * 8;
            #pragma unroll
            for (int tm = 0; tm < 4; tm++) {
                int r = wm + tm*16 + arow;
                ldmx4(ah[tm], Qh + r*SQK + acol);
                ldmx4(al[tm], Ql + r*SQK + acol);
            }
            int brow = ((lane >> 4) << 3) + (lane & 7);
            int bcol = kk + ((lane >> 3) & 1) * 8;
            #pragma unroll
            for (int g = 0; g < 2; g++) {
                uint32_t tt[4];
                int r = wn + g*16 + brow;
                ldmx4(tt, Kh + r*SQK + bcol);
                bh[2*g][0]=tt[0]; bh[2*g][1]=tt[1]; bh[2*g+1][0]=tt[2]; bh[2*g+1][1]=tt[3];
                ldmx4(tt, Kl + r*SQK + bcol);
                bl[2*g][0]=tt[0]; bl[2*g][1]=tt[1]; bl[2*g+1][0]=tt[2]; bl[2*g+1][1]=tt[3];
            }
            #pragma unroll
            for (int tm = 0; tm < 4; tm++)
                #pragma unroll
                for (int tn = 0; tn < 4; tn++) {
                    mma_bf16(s[tm][tn], ah[tm], bh[tn]);
                    mma_bf16(s[tm][tn], ah[tm], bl[tn]);
                    mma_bf16(s[tm][tn], al[tm], bh[tn]);
                }
        }

        int mok[4][2];
        #pragma unroll
        for (int tn=0;tn<4;tn++) {
            int c0 = wn + tn*8 + (lane & 3)*2;
            mok[tn][0] = mcol[c0];
            mok[tn][1] = mcol[c0+1];
        }
        float nmr[4][2], sfv[4][2], lor[4][2], rsum[4][2];
        #pragma unroll
        for (int tm=0;tm<4;tm++) {
            #pragma unroll
            for (int hh=0;hh<2;hh++) {
                float mx = -INFINITY;
                #pragma unroll
                for (int tn=0;tn<4;tn++) {
                    #pragma unroll
                    for (int j=0;j<2;j++) {
                        float v = mok[tn][j] ? s[tm][tn][hh*2+j]*0.125f : -INFINITY;
                        s[tm][tn][hh*2+j] = v;
                        mx = fmaxf(mx, v);
                    }
                }
                mx = fmaxf(mx, __shfl_xor_sync(0xffffffffu, mx, 1));
                mx = fmaxf(mx, __shfl_xor_sync(0xffffffffu, mx, 2));
                nmr[tm][hh] = mx;
            }
        }
        if ((lane & 3) == 0) {
            #pragma unroll
            for (int tm=0;tm<4;tm++)
                #pragma unroll
                for (int hh=0;hh<2;hh++) {
                    int row = wm + tm*16 + (lane >> 2) + hh*8;
                    red[wq*AQ + row] = nmr[tm][hh];
                }
        }
        __syncthreads();
        #pragma unroll
        for (int tm=0;tm<4;tm++) {
            #pragma unroll
            for (int hh=0;hh<2;hh++) {
                int row = wm + tm*16 + (lane >> 2) + hh*8;
                float gm = fmaxf(fmaxf(red[row], red[AQ+row]),
                                 fmaxf(red[2*AQ+row], red[3*AQ+row]));
                float mo = mrow[row];
                float nm = fmaxf(mo, gm);
                float sf = (mo == -INFINITY) ? 0.f : __expf(mo - nm);
                lor[tm][hh] = lrow[row];
                nmr[tm][hh] = nm;
                sfv[tm][hh] = sf;
                rsum[tm][hh] = 0.f;
            }
        }
        #pragma unroll
        for (int tm=0;tm<4;tm++) {
            int r0 = wm + tm*16 + (lane >> 2);
            #pragma unroll
            for (int hh=0;hh<2;hh++) {
                int row = r0 + hh*8;
                float nm = nmr[tm][hh];
                bool dead = (nm == -INFINITY);
                #pragma unroll
                for (int tn=0;tn<4;tn++) {
                    int c0 = wn + tn*8 + (lane & 3)*2;
                    float p0 = dead ? 0.f : __expf(s[tm][tn][hh*2]   - nm);
                    float p1 = dead ? 0.f : __expf(s[tm][tn][hh*2+1] - nm);
                    rsum[tm][hh] += p0 + p1;
                    __nv_bfloat16 h0b = __float2bfloat16(p0);
                    __nv_bfloat16 h1b = __float2bfloat16(p1);
                    __nv_bfloat16 l0b = __float2bfloat16(p0 - __bfloat162float(h0b));
                    __nv_bfloat16 l1b = __float2bfloat16(p1 - __bfloat162float(h1b));
                    *(__nv_bfloat162*)(Ph + row*SVP + c0) = __halves2bfloat162(h0b, h1b);
                    *(__nv_bfloat162*)(Pl + row*SVP + c0) = __halves2bfloat162(l0b, l1b);
                }
                rsum[tm][hh] += __shfl_xor_sync(0xffffffffu, rsum[tm][hh], 1);
                rsum[tm][hh] += __shfl_xor_sync(0xffffffffu, rsum[tm][hh], 2);
            }
        }
        __syncthreads();
        if ((lane & 3) == 0) {
            #pragma unroll
            for (int tm=0;tm<4;tm++)
                #pragma unroll
                for (int hh=0;hh<2;hh++) {
                    int row = wm + tm*16 + (lane >> 2) + hh*8;
                    red[wq*AQ + row] = rsum[tm][hh];
                }
        }
        __syncthreads();
        #pragma unroll
        for (int tm=0;tm<4;tm++) {
            #pragma unroll
            for (int hh=0;hh<2;hh++) {
                int row = wm + tm*16 + (lane >> 2) + hh*8;
                float ts = red[row] + red[AQ+row] + red[2*AQ+row] + red[3*AQ+row];
                float nl = lor[tm][hh]*sfv[tm][hh] + ts;
                if (wq == 0 && (lane & 3) == 0) { mrow[row] = nmr[tm][hh]; lrow[row] = nl; }
            }
        }
        #pragma unroll
        for (int tm=0;tm<4;tm++)
            #pragma unroll
            for (int tn=0;tn<2;tn++)
                #pragma unroll
                for (int r=0;r<4;r++) o[tm][tn][r] *= sfv[tm][r>>1];

        #pragma unroll
        for (int kk = 0; kk < AK; kk += 16) {
            uint32_t ph[4][4], pl[4][4], vh[2][2], vl[2][2];
            int arow = (lane & 15);
            int acol = kk + (lane >> 4) * 8;
            #pragma unroll
            for (int tm = 0; tm < 4; tm++) {
                int r = wm + tm*16 + arow;
                ldmx4(ph[tm], Ph + r*SVP + acol);
                ldmx4(pl[tm], Pl + r*SVP + acol);
            }
            int brow = ((lane >> 4) << 3) + (lane & 7);
            int bcol = kk + ((lane >> 3) & 1) * 8;
            {
                uint32_t tt[4];
                int r = wd + brow;
                ldmx4(tt, Vth + r*SVP + bcol);
                vh[0][0]=tt[0]; vh[0][1]=tt[1]; vh[1][0]=tt[2]; vh[1][1]=tt[3];
                ldmx4(tt, Vtl + r*SVP + bcol);
                vl[0][0]=tt[0]; vl[0][1]=tt[1]; vl[1][0]=tt[2]; vl[1][1]=tt[3];
            }
            #pragma unroll
            for (int tm = 0; tm < 4; tm++)
                #pragma unroll
                for (int tn = 0; tn < 2; tn++) {
                    mma_bf16(o[tm][tn], ph[tm], vh[tn]);
                    mma_bf16(o[tm][tn], ph[tm], vl[tn]);
                    mma_bf16(o[tm][tn], pl[tm], vh[tn]);
                }
        }
    }
    __syncthreads();
    #pragma unroll
    for (int tm=0;tm<4;tm++) {
        int r0 = wm + tm*16 + (lane >> 2);
        float inv0 = 1.f/lrow[r0];
        float inv1 = 1.f/lrow[r0+8];
        #pragma unroll
        for (int tn=0;tn<2;tn++) {
            int cd = wd + tn*8 + (lane & 3)*2;
            size_t base0 = ((size_t)b*Sc + q0 + r0)*Ec + h*HDc + cd;
            float v0 = o[tm][tn][0]*inv0, v1 = o[tm][tn][1]*inv0;
            float v2 = o[tm][tn][2]*inv1, v3 = o[tm][tn][3]*inv1;
            __nv_bfloat16 h0 = __float2bfloat16(v0), h1 = __float2bfloat16(v1);
            __nv_bfloat16 h2 = __float2bfloat16(v2), h3 = __float2bfloat16(v3);
            __nv_bfloat16 l0 = __float2bfloat16(v0 - __bfloat162float(h0));
            __nv_bfloat16 l1 = __float2bfloat16(v1 - __bfloat162float(h1));
            __nv_bfloat16 l2 = __float2bfloat16(v2 - __bfloat162float(h2));
            __nv_bfloat16 l3 = __float2bfloat16(v3 - __bfloat162float(h3));
            *(__nv_bfloat162*)(OgH + base0)        = __halves2bfloat162(h0, h1);
            *(__nv_bfloat162*)(OgH + base0 + 8*Ec) = __halves2bfloat162(h2, h3);
            *(__nv_bfloat162*)(OgL + base0)        = __halves2bfloat162(l0, l1);
            *(__nv_bfloat162*)(OgL + base0 + 8*Ec) = __halves2bfloat162(l2, l3);
        }
    }
}

// ---------------- residual + layernorm (optional bf16 split output) --------
__global__ __launch_bounds__(256) void addln_k(const float* __restrict__ X,
                                               const float* __restrict__ Y,
                                               const float* __restrict__ g,
                                               const float* __restrict__ bb,
                                               float* __restrict__ out,
                                               __nv_bfloat16* __restrict__ outH,
                                               __nv_bfloat16* __restrict__ outL) {
    int row = blockIdx.x;
    size_t base = (size_t)row*Ec;
    int tid = threadIdx.x;
    float v[4];
    double s = 0.0, sq = 0.0;
    #pragma unroll
    for (int u=0;u<4;u++) {
        int i = tid + u*256;
        float t = X[base+i] + Y[base+i];
        v[u] = t;
        s += (double)t; sq += (double)t*(double)t;
    }
    __shared__ double rs[256], rq[256];
    rs[tid]=s; rq[tid]=sq;
    __syncthreads();
    for (int off=128; off>0; off>>=1) {
        if (tid<off) { rs[tid]+=rs[tid+off]; rq[tid]+=rq[tid+off]; }
        __syncthreads();
    }
    double mean = rs[0]/(double)Ec;
    double var  = rq[0]/(double)Ec - mean*mean;
    float inv = (float)(1.0/sqrt(var + 1e-5));
    float mu  = (float)mean;
    #pragma unroll
    for (int u=0;u<4;u++) {
        int i = tid + u*256;
        float r = (v[u]-mu)*inv*g[i] + bb[i];
        out[base+i] = r;
        if (outH) {
            __nv_bfloat16 hb = __float2bfloat16(r);
            outH[base+i] = hb;
            outL[base+i] = __float2bfloat16(r - __bfloat162float(hb));
        }
    }
}

// ---------------- launcher ----------------
extern "C" void kernel_launch(void* const* d_in, const int* in_sizes, int n_in,
                              void* d_out, int out_size) {
    const float* x    = (const float*)d_in[0];
    const int*   mask = (const int*)  d_in[1];
    const float* Wq = (const float*)d_in[2];  const float* bq = (const float*)d_in[3];
    const float* Wk = (const float*)d_in[4];  const float* bk = (const float*)d_in[5];
    const float* Wv = (const float*)d_in[6];  const float* bv = (const float*)d_in[7];
    const float* Wo = (const float*)d_in[8];  const float* bo = (const float*)d_in[9];
    const float* W1 = (const float*)d_in[10]; const float* b1 = (const float*)d_in[11];
    const float* W2 = (const float*)d_in[12]; const float* b2 = (const float*)d_in[13];
    const float* g1 = (const float*)d_in[14]; const float* be1= (const float*)d_in[15];
    const float* g2 = (const float*)d_in[16]; const float* be2= (const float*)d_in[17];

    PP pp;
    pp.W[0]=Wq; pp.W[1]=Wk; pp.W[2]=Wv; pp.W[3]=Wo; pp.W[4]=W1; pp.W[5]=W2;
    pp.N[0]=Ec*Ec; pp.N[1]=Ec*Ec; pp.N[2]=Ec*Ec; pp.N[3]=Ec*Ec;
    pp.N[4]=DFFc*Ec; pp.N[5]=Ec*DFFc;

    const double spA[NM] = {0.25, 0.25, 0.25, 0.3/1.32, 0.375, 0.3125};
    const double spB[NM] = {0.94, 0.94, 0.94, 1.0-0.066, 0.96, 1.0-0.048};
    Ranks rk;
    for (int m=0;m<NM;m++) {
        double iA = spA[m]*(double)(pp.N[m]-1);
        rk.kA[m] = (long long)floor(iA);
        rk.fA[m] = iA - (double)rk.kA[m];
        double iB = spB[m]*(double)(pp.N[m]-1);
        rk.kB[m] = (long long)floor(iB);
        rk.fB[m] = iB - (double)rk.kB[m];
    }

    __nv_bfloat16 *pWhQKV,*pWlQKV,*pWhO,*pWlO,*pWh1,*pWl1,*pWh2,*pWl2;
    __nv_bfloat16 *pXh,*pXl,*pQKVh,*pQKVl,*pAttH,*pAttL,*pX1h,*pX1l,*pFFh,*pFFl;
    float *pBqkv,*pO,*pX1,*pF2;
    cudaGetSymbolAddress((void**)&pWhQKV, g_whQKV);
    cudaGetSymbolAddress((void**)&pWlQKV, g_wlQKV);
    cudaGetSymbolAddress((void**)&pWhO,   g_whO);
    cudaGetSymbolAddress((void**)&pWlO,   g_wlO);
    cudaGetSymbolAddress((void**)&pWh1,   g_wh1);
    cudaGetSymbolAddress((void**)&pWl1,   g_wl1);
    cudaGetSymbolAddress((void**)&pWh2,   g_wh2);
    cudaGetSymbolAddress((void**)&pWl2,   g_wl2);
    cudaGetSymbolAddress((void**)&pBqkv,  g_biasQKV);
    cudaGetSymbolAddress((void**)&pXh,    g_xh);
    cudaGetSymbolAddress((void**)&pXl,    g_xl);
    cudaGetSymbolAddress((void**)&pQKVh,  g_qkvh);
    cudaGetSymbolAddress((void**)&pQKVl,  g_qkvl);
    cudaGetSymbolAddress((void**)&pAttH,  g_atth);
    cudaGetSymbolAddress((void**)&pAttL,  g_attl);
    cudaGetSymbolAddress((void**)&pO,     g_oout);
    cudaGetSymbolAddress((void**)&pX1,    g_x1);
    cudaGetSymbolAddress((void**)&pX1h,   g_x1h);
    cudaGetSymbolAddress((void**)&pX1l,   g_x1l);
    cudaGetSymbolAddress((void**)&pFFh,   g_ffh);
    cudaGetSymbolAddress((void**)&pFFl,   g_ffl);
    cudaGetSymbolAddress((void**)&pF2,    g_f2);

    WSplit ws;
    ws.hi[0]=pWhQKV;         ws.lo[0]=pWlQKV;
    ws.hi[1]=pWhQKV+Ec*Ec;   ws.lo[1]=pWlQKV+Ec*Ec;
    ws.hi[2]=pWhQKV+2*Ec*Ec; ws.lo[2]=pWlQKV+2*Ec*Ec;
    ws.hi[3]=pWhO;           ws.lo[3]=pWlO;
    ws.hi[4]=pWh1;           ws.lo[4]=pWl1;
    ws.hi[5]=pWh2;           ws.lo[5]=pWl2;

    const dim3 hgrid(148, NM);

    // ---- weight preprocessing (scan fused into hist last block) ----
    init_k<<<128,256>>>(rk);
    hist_k<0,0><<<hgrid,256>>>(pp, rk);
    hist_k<0,1><<<hgrid,256>>>(pp, rk);
    hist_k<0,2><<<hgrid,256>>>(pp, rk);
    alpha_k<<<hgrid,256>>>(pp);
    hist_k<1,0><<<hgrid,256>>>(pp, rk);
    hist_k<1,1><<<hgrid,256>>>(pp, rk);
    hist_k<1,2><<<hgrid,256>>>(pp, rk);
    weff_k<<<hgrid,256>>>(pp, ws);
    concat_bias_k<<<(Ec+255)/256,256>>>(bq, bk, bv, pBqkv);
    split_k<<<(Mc*Ec/4+255)/256,256>>>((const float4*)x, pXh, pXl, Mc*Ec/4);

    // ---- tensor-core GEMM setup (2-stage: 80 KB, 2 CTAs/SM) ----
    size_t tc_smem = (size_t)8 * TILE_E * sizeof(__nv_bfloat16);
    cudaFuncSetAttribute(gemm_tc<0>, cudaFuncAttributeMaxDynamicSharedMemorySize, (int)tc_smem);
    cudaFuncSetAttribute(gemm_tc<2>, cudaFuncAttributeMaxDynamicSharedMemorySize, (int)tc_smem);
    cudaFuncSetAttribute(gemm_tc<3>, cudaFuncAttributeMaxDynamicSharedMemorySize, (int)tc_smem);

    // ---- fused QKV projection: route + split bf16 output ----
    gemm_tc<3><<<dim3(3*Ec/TBN, Mc/TBM),256,tc_smem>>>(
        pXh, pXl, pWhQKV, pWlQKV, pBqkv, nullptr, pQKVh, pQKVl, Mc, 3*Ec, Ec);

    // ---- attention (tensor core, split inputs) ----
    size_t at_smem = ATTN_SMEM_BYTES;
    cudaFuncSetAttribute(attn_tc, cudaFuncAttributeMaxDynamicSharedMemorySize, (int)at_smem);
    attn_tc<<<dim3(Sc/AQ, Hc, Bc), 256, at_smem>>>(pQKVh, pQKVl, mask, pAttH, pAttL);

    // ---- output projection + LN1 ----
    dim3 gEE(Ec/TBN, Mc/TBM);
    gemm_tc<0><<<gEE,256,tc_smem>>>(
        pAttH, pAttL, pWhO, pWlO, bo, pO, nullptr, nullptr, Mc, Ec, Ec);
    addln_k<<<Mc,256>>>(x, pO, g1, be1, pX1, pX1h, pX1l);

    // ---- FFN ----
    gemm_tc<2><<<dim3(DFFc/TBN, Mc/TBM),256,tc_smem>>>(
        pX1h, pX1l, pWh1, pWl1, b1, nullptr, pFFh, pFFl, Mc, DFFc, Ec);
    gemm_tc<0><<<gEE,256,tc_smem>>>(
        pFFh, pFFl, pWh2, pWl2, b2, pF2, nullptr, nullptr, Mc, Ec, DFFc);
    addln_k<<<Mc,256>>>(pX1, pF2, g2, be2, (float*)d_out, nullptr, nullptr);
}

// round 17
// speedup vs baseline: 1.0104x; 1.0104x over previous
#include <cuda_runtime.h>
#include <cuda_bf16.h>
#include <math.h>
#include <stdint.h>

// ---------------- problem constants ----------------
#define Bc 2
#define Sc 2048
#define Ec 1024
#define Hc 16
#define HDc 64
#define DFFc 4096
#define Mc (Bc*Sc)          // 4096 tokens
#define NM 6                // Wq Wk Wv Wo W1 W2
#define ROUTE_THR 0.05f

// ---------------- device scratch (no allocations allowed) ----------------
__device__ __nv_bfloat16 g_whQKV[3*Ec*Ec];
__device__ __nv_bfloat16 g_wlQKV[3*Ec*Ec];
__device__ __nv_bfloat16 g_whO[Ec*Ec];
__device__ __nv_bfloat16 g_wlO[Ec*Ec];
__device__ __nv_bfloat16 g_wh1[DFFc*Ec];
__device__ __nv_bfloat16 g_wl1[DFFc*Ec];
__device__ __nv_bfloat16 g_wh2[Ec*DFFc];
__device__ __nv_bfloat16 g_wl2[Ec*DFFc];
__device__ float g_biasQKV[3*Ec];

__device__ __nv_bfloat16 g_xh[Mc*Ec];
__device__ __nv_bfloat16 g_xl[Mc*Ec];
__device__ __nv_bfloat16 g_qkvh[Mc*3*Ec];
__device__ __nv_bfloat16 g_qkvl[Mc*3*Ec];
__device__ __nv_bfloat16 g_atth[Mc*Ec];
__device__ __nv_bfloat16 g_attl[Mc*Ec];
__device__ float g_oout[Mc*Ec];
__device__ float g_x1[Mc*Ec];
__device__ __nv_bfloat16 g_x1h[Mc*Ec];
__device__ __nv_bfloat16 g_x1l[Mc*Ec];
__device__ __nv_bfloat16 g_ffh[Mc*DFFc];
__device__ __nv_bfloat16 g_ffl[Mc*DFFc];
__device__ float g_f2[Mc*Ec];

// selection state
struct SelSt {
    unsigned long long rk, rk1;
    unsigned pref, pref1;
    unsigned val, val1;
};
__device__ SelSt    g_sel[2][NM];
__device__ unsigned g_hist[2][3][NM][2][2048];
__device__ unsigned g_cnt[2][3][NM];
__device__ unsigned g_cntAl[NM];
__device__ float    g_thr[NM], g_alpha[NM], g_rthr[NM];
__device__ double   g_aSum[NM];
__device__ unsigned long long g_aCnt[NM];

struct PP { const float* W[NM]; int N[NM]; };
struct Ranks { long long kA[NM]; double fA[NM]; long long kB[NM]; double fB[NM]; };
struct WSplit { __nv_bfloat16* hi[NM]; __nv_bfloat16* lo[NM]; };

// ---------------- init / zero ----------------
__global__ void init_k(Ranks r) {
    int t = blockIdx.x*blockDim.x + threadIdx.x;
    int total = 2*3*NM*2*2048;
    unsigned* h = &g_hist[0][0][0][0][0];
    for (int i = t; i < total; i += gridDim.x*blockDim.x) h[i] = 0u;
    if (t < 2*3*NM) (&g_cnt[0][0][0])[t] = 0u;
    if (t < NM) {
        g_cntAl[t] = 0u;
        SelSt s0; s0.rk = (unsigned long long)r.kA[t]; s0.rk1 = s0.rk + 1ULL;
        s0.pref = 0; s0.pref1 = 0; s0.val = 0; s0.val1 = 0;
        g_sel[0][t] = s0;
        SelSt s1; s1.rk = (unsigned long long)r.kB[t]; s1.rk1 = s1.rk + 1ULL;
        s1.pref = 0; s1.pref1 = 0; s1.val = 0; s1.val1 = 0;
        g_sel[1][t] = s1;
        g_aSum[t] = 0.0; g_aCnt[t] = 0ULL;
    }
}

// ---------------- histogram passes (MLP=4, fused last-block scan) ---------
template<int STAGE, int LEVEL>
__global__ __launch_bounds__(256) void hist_k(PP pp, Ranks rkk) {
    __shared__ unsigned h0[2048];
    __shared__ unsigned h1[2048];
    __shared__ bool isLast;
    int m = blockIdx.y;
    int N4 = pp.N[m] >> 2;
    const float4* __restrict__ W = (const float4*)pp.W[m];
    for (int i = threadIdx.x; i < 2048; i += blockDim.x) { h0[i]=0u; h1[i]=0u; }
    unsigned p0=0, p1=0;
    if (LEVEL > 0) { p0 = g_sel[STAGE][m].pref; p1 = g_sel[STAGE][m].pref1; }
    float thr=0.f, alpha=0.f;
    if (STAGE==1) { thr = g_thr[m]; alpha = g_alpha[m]; }
    __syncthreads();
    unsigned* rep = ((threadIdx.x >> 5) & 1) ? h1 : h0;

    auto proc = [&](float4 w4) {
        float wv[4] = {w4.x, w4.y, w4.z, w4.w};
        #pragma unroll
        for (int u = 0; u < 4; u++) {
            float w = wv[u];
            float a = fabsf(w);
            unsigned bits;
            if (STAGE==0) bits = __float_as_uint(a);
            else {
                float wq = (a > thr) ? copysignf(alpha, w) : 0.0f;
                bits = __float_as_uint(fabsf(w - wq));
            }
            if (LEVEL==0) {
                atomicAdd(&rep[bits>>21], 1u);
            } else if (LEVEL==1) {
                if ((bits>>21)==p0) atomicAdd(&h0[(bits>>10)&2047u], 1u);
                if ((bits>>21)==p1) atomicAdd(&h1[(bits>>10)&2047u], 1u);
            } else {
                if ((bits>>10)==p0) atomicAdd(&h0[bits&1023u], 1u);
                if ((bits>>10)==p1) atomicAdd(&h1[bits&1023u], 1u);
            }
        }
    };

    int stride = gridDim.x*blockDim.x;
    int i = blockIdx.x*blockDim.x + threadIdx.x;
    for (; i + 3*stride < N4; i += 4*stride) {
        float4 q0 = W[i], q1 = W[i+stride], q2 = W[i+2*stride], q3 = W[i+3*stride];
        proc(q0); proc(q1); proc(q2); proc(q3);
    }
    for (; i < N4; i += stride) proc(W[i]);

    __syncthreads();
    const int nb = (LEVEL==2) ? 1024 : 2048;
    if (LEVEL==0) {
        for (int j = threadIdx.x; j < 2048; j += blockDim.x) {
            unsigned v = h0[j] + h1[j];
            if (v) atomicAdd(&g_hist[STAGE][LEVEL][m][0][j], v);
        }
    } else {
        for (int j = threadIdx.x; j < nb; j += blockDim.x) {
            if (h0[j]) atomicAdd(&g_hist[STAGE][LEVEL][m][0][j], h0[j]);
            if (h1[j]) atomicAdd(&g_hist[STAGE][LEVEL][m][1][j], h1[j]);
        }
    }
    __threadfence();
    __syncthreads();
    if (threadIdx.x == 0) {
        unsigned done = atomicAdd(&g_cnt[STAGE][LEVEL][m], 1u);
        isLast = (done == gridDim.x - 1);
    }
    __syncthreads();
    if (!isLast) return;

    volatile unsigned* gh0 = g_hist[STAGE][LEVEL][m][0];
    volatile unsigned* gh1 = g_hist[STAGE][LEVEL][m][1];
    for (int j = threadIdx.x; j < nb; j += blockDim.x) {
        unsigned a = gh0[j];
        h0[j] = a;
        h1[j] = (LEVEL==0) ? a : gh1[j];
    }
    __syncthreads();
    if (threadIdx.x < 2) {
        int which = threadIdx.x;
        SelSt s = g_sel[STAGE][m];
        unsigned long long rank = which ? s.rk1 : s.rk;
        unsigned pref = which ? s.pref1 : s.pref;
        unsigned long long c = 0;
        int bsel = 0;
        unsigned* hh = which ? h1 : h0;
        for (int b = 0; b < nb; b++) {
            c += hh[b];
            if (c > rank) { bsel = b; rank -= (c - hh[b]); break; }
        }
        if (LEVEL==0)      pref = (unsigned)bsel;
        else if (LEVEL==1) pref = (pref<<11) | (unsigned)bsel;
        else {
            unsigned val = (pref<<10) | (unsigned)bsel;
            if (which) g_sel[STAGE][m].val1 = val; else g_sel[STAGE][m].val = val;
        }
        if (LEVEL < 2) {
            if (which) { g_sel[STAGE][m].pref1 = pref; g_sel[STAGE][m].rk1 = rank; }
            else       { g_sel[STAGE][m].pref  = pref; g_sel[STAGE][m].rk  = rank; }
        }
    }
    if (LEVEL==2) {
        __syncthreads();
        if (threadIdx.x==0) {
            double a0 = (double)__uint_as_float(g_sel[STAGE][m].val);
            double a1 = (double)__uint_as_float(g_sel[STAGE][m].val1);
            double f  = (STAGE==1) ? rkk.fB[m] : rkk.fA[m];
            float t = (float)(a0 + f*(a1-a0));
            if (STAGE==0) g_thr[m] = t; else g_rthr[m] = t;
        }
    }
}

// ---------------- alpha (MLP=4, fused finalize) ----------------
__global__ __launch_bounds__(256) void alpha_k(PP pp) {
    int m = blockIdx.y;
    int N4 = pp.N[m] >> 2;
    const float4* __restrict__ W = (const float4*)pp.W[m];
    float thr = g_thr[m];
    double s = 0.0; unsigned long long c = 0ULL;

    auto proc = [&](float4 w4) {
        float av[4] = {fabsf(w4.x), fabsf(w4.y), fabsf(w4.z), fabsf(w4.w)};
        #pragma unroll
        for (int u = 0; u < 4; u++)
            if (av[u] > thr) { s += (double)av[u]; c++; }
    };
    int stride = gridDim.x*blockDim.x;
    int i = blockIdx.x*blockDim.x + threadIdx.x;
    for (; i + 3*stride < N4; i += 4*stride) {
        float4 q0 = W[i], q1 = W[i+stride], q2 = W[i+2*stride], q3 = W[i+3*stride];
        proc(q0); proc(q1); proc(q2); proc(q3);
    }
    for (; i < N4; i += stride) proc(W[i]);

    __shared__ double sd[256];
    __shared__ unsigned long long sc[256];
    __shared__ bool isLastA;
    int tid = threadIdx.x;
    sd[tid] = s; sc[tid] = c;
    __syncthreads();
    for (int off = 128; off > 0; off >>= 1) {
        if (tid < off) { sd[tid] += sd[tid+off]; sc[tid] += sc[tid+off]; }
        __syncthreads();
    }
    if (tid==0) {
        atomicAdd(&g_aSum[m], sd[0]);
        atomicAdd(&g_aCnt[m], sc[0]);
    }
    __threadfence();
    __syncthreads();
    if (tid==0) {
        unsigned done = atomicAdd(&g_cntAl[m], 1u);
        isLastA = (done == gridDim.x - 1);
    }
    __syncthreads();
    if (isLastA && tid==0) {
        double ssum = *((volatile double*)&g_aSum[m]);
        unsigned long long cc = *((volatile unsigned long long*)&g_aCnt[m]);
        double cd = (double)cc; if (cd < 1.0) cd = 1.0;
        g_alpha[m] = (float)(ssum/cd);
    }
}

// ---------------- effective weight write: split bf16 hi/lo (MLP=4) ----------
__global__ __launch_bounds__(256) void weff_k(PP pp, WSplit ws) {
    int m = blockIdx.y;
    int N4 = pp.N[m] >> 2;
    const float4* __restrict__ W = (const float4*)pp.W[m];
    __nv_bfloat16* __restrict__ OH = ws.hi[m];
    __nv_bfloat16* __restrict__ OL = ws.lo[m];
    float thr = g_thr[m], alpha = g_alpha[m], rthr = g_rthr[m];

    auto proc = [&](float4 w4, int idx4) {
        float wv[4] = {w4.x, w4.y, w4.z, w4.w};
        __nv_bfloat16 hb[4], lb[4];
        #pragma unroll
        for (int u = 0; u < 4; u++) {
            float w = wv[u];
            float a = fabsf(w);
            float wq = (a > thr) ? copysignf(alpha, w) : 0.0f;
            float rr = w - wq;
            float o = wq + ((fabsf(rr) >= rthr) ? rr : 0.0f);
            hb[u] = __float2bfloat16(o);
            lb[u] = __float2bfloat16(o - __bfloat162float(hb[u]));
        }
        int off = idx4*4;
        *(__nv_bfloat162*)(OH+off)   = __halves2bfloat162(hb[0], hb[1]);
        *(__nv_bfloat162*)(OH+off+2) = __halves2bfloat162(hb[2], hb[3]);
        *(__nv_bfloat162*)(OL+off)   = __halves2bfloat162(lb[0], lb[1]);
        *(__nv_bfloat162*)(OL+off+2) = __halves2bfloat162(lb[2], lb[3]);
    };
    int stride = gridDim.x*blockDim.x;
    int i = blockIdx.x*blockDim.x + threadIdx.x;
    for (; i + 3*stride < N4; i += 4*stride) {
        float4 q0 = W[i], q1 = W[i+stride], q2 = W[i+2*stride], q3 = W[i+3*stride];
        proc(q0, i); proc(q1, i+stride); proc(q2, i+2*stride); proc(q3, i+3*stride);
    }
    for (; i < N4; i += stride) proc(W[i], i);
}

__global__ void concat_bias_k(const float* __restrict__ bq, const float* __restrict__ bk,
                              const float* __restrict__ bv, float* __restrict__ out) {
    int i = blockIdx.x*blockDim.x + threadIdx.x;
    if (i < Ec) { out[i] = bq[i]; out[Ec+i] = bk[i]; out[2*Ec+i] = bv[i]; }
}

// ---------------- split fp32 -> bf16 hi/lo ----------------
__global__ __launch_bounds__(256) void split_k(const float4* __restrict__ X,
                                               __nv_bfloat16* __restrict__ H,
                                               __nv_bfloat16* __restrict__ L,
                                               int n4) {
    int i = blockIdx.x*blockDim.x + threadIdx.x;
    if (i >= n4) return;
    float4 v = X[i];
    float f[4] = {v.x, v.y, v.z, v.w};
    __nv_bfloat16 hb[4], lb[4];
    #pragma unroll
    for (int u=0;u<4;u++) {
        hb[u] = __float2bfloat16(f[u]);
        lb[u] = __float2bfloat16(f[u] - __bfloat162float(hb[u]));
    }
    int off = i*4;
    *(__nv_bfloat162*)(H+off)   = __halves2bfloat162(hb[0], hb[1]);
    *(__nv_bfloat162*)(H+off+2) = __halves2bfloat162(hb[2], hb[3]);
    *(__nv_bfloat162*)(L+off)   = __halves2bfloat162(lb[0], lb[1]);
    *(__nv_bfloat162*)(L+off+2) = __halves2bfloat162(lb[2], lb[3]);
}

// ---------------- tensor-core helpers ----------------
__device__ __forceinline__ float gelu_exact(float v) {
    return 0.5f*v*(1.0f + erff(v*0.70710678118654752440f));
}

__device__ __forceinline__ void ldmx4(uint32_t* r, const __nv_bfloat16* p) {
    unsigned a = (unsigned)__cvta_generic_to_shared(p);
    asm volatile("ldmatrix.sync.aligned.m8n8.x4.shared.b16 {%0,%1,%2,%3}, [%4];"
        : "=r"(r[0]), "=r"(r[1]), "=r"(r[2]), "=r"(r[3]) : "r"(a));
}

__device__ __forceinline__ void mma_bf16(float* c, const uint32_t* a, const uint32_t* b) {
    asm volatile("mma.sync.aligned.m16n8k16.row.col.f32.bf16.bf16.f32 "
        "{%0,%1,%2,%3}, {%4,%5,%6,%7}, {%8,%9}, {%0,%1,%2,%3};"
        : "+f"(c[0]), "+f"(c[1]), "+f"(c[2]), "+f"(c[3])
        : "r"(a[0]), "r"(a[1]), "r"(a[2]), "r"(a[3]), "r"(b[0]), "r"(b[1]));
}

__device__ __forceinline__ void cpasync16(__nv_bfloat16* dst, const __nv_bfloat16* src) {
    unsigned d = (unsigned)__cvta_generic_to_shared(dst);
    asm volatile("cp.async.ca.shared.global [%0], [%1], 16;" :: "r"(d), "l"(src));
}

// ---------------- tensor-core GEMM (pre-split operands, 2-stage cp.async) --
#define TBM 128
#define TBN 128
#define TBK 32
#define LDT 40
#define TILE_E (TBM*LDT)

template<int EPI>   // 0=none(fp32) 2=gelu(bf16 split out) 3=route(bf16 split out)
__global__ __launch_bounds__(256) void gemm_tc(const __nv_bfloat16* __restrict__ AH,
                                               const __nv_bfloat16* __restrict__ AL,
                                               const __nv_bfloat16* __restrict__ BH,
                                               const __nv_bfloat16* __restrict__ BL,
                                               const float* __restrict__ bias,
                                               float* __restrict__ Cf,
                                               __nv_bfloat16* __restrict__ CH,
                                               __nv_bfloat16* __restrict__ CL,
                                               int M, int N, int K) {
    extern __shared__ __nv_bfloat16 sh[];
    const int m0 = blockIdx.y*TBM, n0 = blockIdx.x*TBN;
    const int tid = threadIdx.x;
    const int lane = tid & 31;
    const int wid = tid >> 5;
    const int wm = (wid >> 2) * 64;
    const int wn = (wid & 3) * 32;

    float acc[4][4][4];
    #pragma unroll
    for (int i=0;i<4;i++)
        #pragma unroll
        for (int j=0;j<4;j++)
            #pragma unroll
            for (int r=0;r<4;r++) acc[i][j][r] = 0.f;

    const __nv_bfloat16* base0 = AH + (size_t)m0*K;
    const __nv_bfloat16* base1 = AL + (size_t)m0*K;
    const __nv_bfloat16* base2 = BH + (size_t)n0*K;
    const __nv_bfloat16* base3 = BL + (size_t)n0*K;

    auto issue = [&](int ch, int s) {
        int k0 = ch*TBK;
        __nv_bfloat16* dst = sh + s*4*TILE_E;
        #pragma unroll
        for (int j = 0; j < 8; j++) {
            const int arr = j >> 1;
            int e = tid + (j & 1)*256;
            int r = e >> 2, c = (e & 3) * 8;
            const __nv_bfloat16* src =
                (arr==0 ? base0 : arr==1 ? base1 : arr==2 ? base2 : base3)
                + (size_t)r*K + k0 + c;
            cpasync16(dst + arr*TILE_E + r*LDT + c, src);
        }
    };

    const int nch = K / TBK;
    issue(0, 0);
    asm volatile("cp.async.commit_group;");

    for (int ch = 0; ch < nch; ch++) {
        const int cur = ch & 1;
        if (ch + 1 < nch) {
            issue(ch+1, cur^1);
            asm volatile("cp.async.commit_group;");
            asm volatile("cp.async.wait_group 1;");
        } else {
            asm volatile("cp.async.wait_group 0;");
        }
        __syncthreads();

        const __nv_bfloat16* Ah = sh + cur*4*TILE_E;
        const __nv_bfloat16* Al = Ah + TILE_E;
        const __nv_bfloat16* Bh = Ah + 2*TILE_E;
        const __nv_bfloat16* Bl = Ah + 3*TILE_E;

        #pragma unroll
        for (int kk = 0; kk < TBK; kk += 16) {
            uint32_t ah[4][4], al[4][4], bh[4][2], bl[4][2];
            int arow = (lane & 15);
            int acol = kk + (lane >> 4) * 8;
            #pragma unroll
            for (int tm = 0; tm < 4; tm++) {
                int r = wm + tm*16 + arow;
                ldmx4(ah[tm], Ah + r*LDT + acol);
                ldmx4(al[tm], Al + r*LDT + acol);
            }
            int brow = ((lane >> 4) << 3) + (lane & 7);
            int bcol = kk + ((lane >> 3) & 1) * 8;
            #pragma unroll
            for (int g = 0; g < 2; g++) {
                uint32_t t[4];
                int r = wn + g*16 + brow;
                ldmx4(t, Bh + r*LDT + bcol);
                bh[2*g][0]=t[0]; bh[2*g][1]=t[1]; bh[2*g+1][0]=t[2]; bh[2*g+1][1]=t[3];
                ldmx4(t, Bl + r*LDT + bcol);
                bl[2*g][0]=t[0]; bl[2*g][1]=t[1]; bl[2*g+1][0]=t[2]; bl[2*g+1][1]=t[3];
            }
            #pragma unroll
            for (int tm = 0; tm < 4; tm++)
                #pragma unroll
                for (int tn = 0; tn < 4; tn++) {
                    mma_bf16(acc[tm][tn], ah[tm], bh[tn]);
                    mma_bf16(acc[tm][tn], ah[tm], bl[tn]);
                    mma_bf16(acc[tm][tn], al[tm], bh[tn]);
                }
        }
        __syncthreads();
    }

    #pragma unroll
    for (int tm = 0; tm < 4; tm++) {
        #pragma unroll
        for (int tn = 0; tn < 4; tn++) {
            int row = m0 + wm + tm*16 + (lane >> 2);
            int col = n0 + wn + tn*8 + (lane & 3)*2;
            float b0 = bias[col], b1 = bias[col+1];
            float v0 = acc[tm][tn][0] + b0;
            float v1 = acc[tm][tn][1] + b1;
            float v2 = acc[tm][tn][2] + b0;
            float v3 = acc[tm][tn][3] + b1;
            if (EPI==3) {
                v0 = (fabsf(v0) > ROUTE_THR) ? v0 : 0.0f;
                v1 = (fabsf(v1) > ROUTE_THR) ? v1 : 0.0f;
                v2 = (fabsf(v2) > ROUTE_THR) ? v2 : 0.0f;
                v3 = (fabsf(v3) > ROUTE_THR) ? v3 : 0.0f;
            }
            if (EPI==2) {
                v0 = gelu_exact(v0); v1 = gelu_exact(v1);
                v2 = gelu_exact(v2); v3 = gelu_exact(v3);
            }
            if (EPI==2 || EPI==3) {
                __nv_bfloat16 h0 = __float2bfloat16(v0), h1 = __float2bfloat16(v1);
                __nv_bfloat16 h2 = __float2bfloat16(v2), h3 = __float2bfloat16(v3);
                __nv_bfloat16 l0 = __float2bfloat16(v0 - __bfloat162float(h0));
                __nv_bfloat16 l1 = __float2bfloat16(v1 - __bfloat162float(h1));
                __nv_bfloat16 l2 = __float2bfloat16(v2 - __bfloat162float(h2));
                __nv_bfloat16 l3 = __float2bfloat16(v3 - __bfloat162float(h3));
                *(__nv_bfloat162*)(CH + (size_t)row*N + col)     = __halves2bfloat162(h0, h1);
                *(__nv_bfloat162*)(CH + (size_t)(row+8)*N + col) = __halves2bfloat162(h2, h3);
                *(__nv_bfloat162*)(CL + (size_t)row*N + col)     = __halves2bfloat162(l0, l1);
                *(__nv_bfloat162*)(CL + (size_t)(row+8)*N + col) = __halves2bfloat162(l2, l3);
            } else {
                *(float2*)(Cf + (size_t)row*N + col)     = make_float2(v0, v1);
                *(float2*)(Cf + (size_t)(row+8)*N + col) = make_float2(v2, v3);
            }
        }
    }
}

// ---------------- tensor-core flash attention (split QKV inputs) ----------
#define AQ 128
#define AK 128
#define SQK 72
#define SVP 136
#define ATTN_SMEM_BYTES ((2*AQ*SQK + 2*AK*SQK + 2*HDc*SVP + 2*AQ*SVP)*2 + (AQ+AQ+4*AQ)*4 + AK*4)

__global__ __launch_bounds__(256) void attn_tc(const __nv_bfloat16* __restrict__ QKVH,
                                               const __nv_bfloat16* __restrict__ QKVL,
                                               const int* __restrict__ mask,
                                               __nv_bfloat16* __restrict__ OgH,
                                               __nv_bfloat16* __restrict__ OgL) {
    extern __shared__ __nv_bfloat16 sb[];
    __nv_bfloat16* Qh  = sb;
    __nv_bfloat16* Ql  = Qh  + AQ*SQK;
    __nv_bfloat16* Kh  = Ql  + AQ*SQK;
    __nv_bfloat16* Kl  = Kh  + AK*SQK;
    __nv_bfloat16* Vth = Kl  + AK*SQK;
    __nv_bfloat16* Vtl = Vth + HDc*SVP;
    __nv_bfloat16* Ph  = Vtl + HDc*SVP;
    __nv_bfloat16* Pl  = Ph  + AQ*SVP;
    float* mrow = (float*)(Pl + AQ*SVP);
    float* lrow = mrow + AQ;
    float* red  = lrow + AQ;
    int*   mcol = (int*)(red + 4*AQ);

    const int tid = threadIdx.x, lane = tid & 31, wid = tid >> 5;
    const int b = blockIdx.z, h = blockIdx.y, q0 = blockIdx.x*AQ;
    const int E3 = 3*Ec;
    const __nv_bfloat16* QgH = QKVH + ((size_t)b*Sc + q0)*E3 + h*HDc;
    const __nv_bfloat16* QgL = QKVL + ((size_t)b*Sc + q0)*E3 + h*HDc;
    const __nv_bfloat16* KgH = QKVH + (size_t)b*Sc*E3 + Ec + h*HDc;
    const __nv_bfloat16* KgL = QKVL + (size_t)b*Sc*E3 + Ec + h*HDc;
    const __nv_bfloat16* VgH = QKVH + (size_t)b*Sc*E3 + 2*Ec + h*HDc;
    const __nv_bfloat16* VgL = QKVL + (size_t)b*Sc*E3 + 2*Ec + h*HDc;

    for (int i = tid; i < AQ*8; i += 256) {
        int r = i >> 3, c = (i & 7) * 8;
        cpasync16(Qh + r*SQK + c, QgH + (size_t)r*E3 + c);
        cpasync16(Ql + r*SQK + c, QgL + (size_t)r*E3 + c);
    }
    if (tid < AQ) { mrow[tid] = -INFINITY; lrow[tid] = 0.f; }

    const int wm = (wid >> 2) * 64;
    const int wn = (wid & 3) * 32;
    const int wd = (wid & 3) * 16;
    const int wq = wid & 3;

    float o[4][2][4];
    #pragma unroll
    for (int i=0;i<4;i++)
        #pragma unroll
        for (int j=0;j<2;j++)
            #pragma unroll
            for (int r=0;r<4;r++) o[i][j][r] = 0.f;

    for (int t = 0; t < Sc/AK; t++) {
        __syncthreads();
        for (int i = tid; i < AK*8; i += 256) {
            int r = i >> 3, c = (i & 7) * 8;
            size_t g = (size_t)(t*AK + r)*E3 + c;
            cpasync16(Kh + r*SQK + c, KgH + g);
            cpasync16(Kl + r*SQK + c, KgL + g);
        }
        asm volatile("cp.async.commit_group;");
        for (int i = tid; i < AK*8; i += 256) {
            int r = i >> 3, c = (i & 7) * 8;
            size_t g = (size_t)(t*AK + r)*E3 + c;
            uint4 vh4 = *(const uint4*)(VgH + g);
            uint4 vl4 = *(const uint4*)(VgL + g);
            const __nv_bfloat16* hs = (const __nv_bfloat16*)&vh4;
            const __nv_bfloat16* ls = (const __nv_bfloat16*)&vl4;
            #pragma unroll
            for (int u=0;u<8;u++) {
                Vth[(c+u)*SVP + r] = hs[u];
                Vtl[(c+u)*SVP + r] = ls[u];
            }
        }
        if (tid < AK) mcol[tid] = mask[b*Sc + t*AK + tid];
        asm volatile("cp.async.wait_group 0;");
        __syncthreads();

        float s[4][4][4];
        #pragma unroll
        for (int i=0;i<4;i++)
            #pragma unroll
            for (int j=0;j<4;j++)
                #pragma unroll
                for (int r=0;r<4;r++) s[i][j][r] = 0.f;

        #pragma unroll
        for (int kk = 0; kk < HDc; kk += 16) {
            uint32_t ah[4][4], al[4][4], bh[4][2], bl[4][2];
            int arow = (lane & 15);
            int acol = kk + (lane >> 4) * 8;
            #pragma unroll
            for (int tm = 0; tm < 4; tm++) {
                int r = wm + tm*16 + arow;
                ldmx4(ah[tm], Qh + r*SQK + acol);
                ldmx4(al[tm], Ql + r*SQK + acol);
            }
            int brow = ((lane >> 4) << 3) + (lane & 7);
            int bcol = kk + ((lane >> 3) & 1) * 8;
            #pragma unroll
            for (int g = 0; g < 2; g++) {
                uint32_t tt[4];
                int r = wn + g*16 + brow;
                ldmx4(tt, Kh + r*SQK + bcol);
                bh[2*g][0]=tt[0]; bh[2*g][1]=tt[1]; bh[2*g+1][0]=tt[2]; bh[2*g+1][1]=tt[3];
                ldmx4(tt, Kl + r*SQK + bcol);
                bl[2*g][0]=tt[0]; bl[2*g][1]=tt[1]; bl[2*g+1][0]=tt[2]; bl[2*g+1][1]=tt[3];
            }
            #pragma unroll
            for (int tm = 0; tm < 4; tm++)
                #pragma unroll
                for (int tn = 0; tn < 4; tn++) {
                    mma_bf16(s[tm][tn], ah[tm], bh[tn]);
                    mma_bf16(s[tm][tn], ah[tm], bl[tn]);
                    mma_bf16(s[tm][tn], al[tm], bh[tn]);
                }
        }

        int mok[4][2];
        #pragma unroll
        for (int tn=0;tn<4;tn++) {
            int c0 = wn + tn*8 + (lane & 3)*2;
            mok[tn][0] = mcol[c0];
            mok[tn][1] = mcol[c0+1];
        }
        float nmr[4][2], sfv[4][2], lor[4][2], rsum[4][2];
        #pragma unroll
        for (int tm=0;tm<4;tm++) {
            #pragma unroll
            for (int hh=0;hh<2;hh++) {
                float mx = -INFINITY;
                #pragma unroll
                for (int tn=0;tn<4;tn++) {
                    #pragma unroll
                    for (int j=0;j<2;j++) {
                        float v = mok[tn][j] ? s[tm][tn][hh*2+j]*0.125f : -INFINITY;
                        s[tm][tn][hh*2+j] = v;
                        mx = fmaxf(mx, v);
                    }
                }
                mx = fmaxf(mx, __shfl_xor_sync(0xffffffffu, mx, 1));
                mx = fmaxf(mx, __shfl_xor_sync(0xffffffffu, mx, 2));
                nmr[tm][hh] = mx;
            }
        }
        if ((lane & 3) == 0) {
            #pragma unroll
            for (int tm=0;tm<4;tm++)
                #pragma unroll
                for (int hh=0;hh<2;hh++) {
                    int row = wm + tm*16 + (lane >> 2) + hh*8;
                    red[wq*AQ + row] = nmr[tm][hh];
                }
        }
        __syncthreads();
        #pragma unroll
        for (int tm=0;tm<4;tm++) {
            #pragma unroll
            for (int hh=0;hh<2;hh++) {
                int row = wm + tm*16 + (lane >> 2) + hh*8;
                float gm = fmaxf(fmaxf(red[row], red[AQ+row]),
                                 fmaxf(red[2*AQ+row], red[3*AQ+row]));
                float mo = mrow[row];
                float nm = fmaxf(mo, gm);
                float sf = (mo == -INFINITY) ? 0.f : __expf(mo - nm);
                lor[tm][hh] = lrow[row];
                nmr[tm][hh] = nm;
                sfv[tm][hh] = sf;
                rsum[tm][hh] = 0.f;
            }
        }
        #pragma unroll
        for (int tm=0;tm<4;tm++) {
            int r0 = wm + tm*16 + (lane >> 2);
            #pragma unroll
            for (int hh=0;hh<2;hh++) {
                int row = r0 + hh*8;
                float nm = nmr[tm][hh];
                bool dead = (nm == -INFINITY);
                #pragma unroll
                for (int tn=0;tn<4;tn++) {
                    int c0 = wn + tn*8 + (lane & 3)*2;
                    float p0 = dead ? 0.f : __expf(s[tm][tn][hh*2]   - nm);
                    float p1 = dead ? 0.f : __expf(s[tm][tn][hh*2+1] - nm);
                    rsum[tm][hh] += p0 + p1;
                    __nv_bfloat16 h0b = __float2bfloat16(p0);
                    __nv_bfloat16 h1b = __float2bfloat16(p1);
                    __nv_bfloat16 l0b = __float2bfloat16(p0 - __bfloat162float(h0b));
                    __nv_bfloat16 l1b = __float2bfloat16(p1 - __bfloat162float(h1b));
                    *(__nv_bfloat162*)(Ph + row*SVP + c0) = __halves2bfloat162(h0b, h1b);
                    *(__nv_bfloat162*)(Pl + row*SVP + c0) = __halves2bfloat162(l0b, l1b);
                }
                rsum[tm][hh] += __shfl_xor_sync(0xffffffffu, rsum[tm][hh], 1);
                rsum[tm][hh] += __shfl_xor_sync(0xffffffffu, rsum[tm][hh], 2);
            }
        }
        __syncthreads();
        if ((lane & 3) == 0) {
            #pragma unroll
            for (int tm=0;tm<4;tm++)
                #pragma unroll
                for (int hh=0;hh<2;hh++) {
                    int row = wm + tm*16 + (lane >> 2) + hh*8;
                    red[wq*AQ + row] = rsum[tm][hh];
                }
        }
        __syncthreads();
        #pragma unroll
        for (int tm=0;tm<4;tm++) {
            #pragma unroll
            for (int hh=0;hh<2;hh++) {
                int row = wm + tm*16 + (lane >> 2) + hh*8;
                float ts = red[row] + red[AQ+row] + red[2*AQ+row] + red[3*AQ+row];
                float nl = lor[tm][hh]*sfv[tm][hh] + ts;
                if (wq == 0 && (lane & 3) == 0) { mrow[row] = nmr[tm][hh]; lrow[row] = nl; }
            }
        }
        #pragma unroll
        for (int tm=0;tm<4;tm++)
            #pragma unroll
            for (int tn=0;tn<2;tn++)
                #pragma unroll
                for (int r=0;r<4;r++) o[tm][tn][r] *= sfv[tm][r>>1];

        #pragma unroll
        for (int kk = 0; kk < AK; kk += 16) {
            uint32_t ph[4][4], pl[4][4], vh[2][2], vl[2][2];
            int arow = (lane & 15);
            int acol = kk + (lane >> 4) * 8;
            #pragma unroll
            for (int tm = 0; tm < 4; tm++) {
                int r = wm + tm*16 + arow;
                ldmx4(ph[tm], Ph + r*SVP + acol);
                ldmx4(pl[tm], Pl + r*SVP + acol);
            }
            int brow = ((lane >> 4) << 3) + (lane & 7);
            int bcol = kk + ((lane >> 3) & 1) * 8;
            {
                uint32_t tt[4];
                int r = wd + brow;
                ldmx4(tt, Vth + r*SVP + bcol);
                vh[0][0]=tt[0]; vh[0][1]=tt[1]; vh[1][0]=tt[2]; vh[1][1]=tt[3];
                ldmx4(tt, Vtl + r*SVP + bcol);
                vl[0][0]=tt[0]; vl[0][1]=tt[1]; vl[1][0]=tt[2]; vl[1][1]=tt[3];
            }
            #pragma unroll
            for (int tm = 0; tm < 4; tm++)
                #pragma unroll
                for (int tn = 0; tn < 2; tn++) {
                    mma_bf16(o[tm][tn], ph[tm], vh[tn]);
                    mma_bf16(o[tm][tn], ph[tm], vl[tn]);
                    mma_bf16(o[tm][tn], pl[tm], vh[tn]);
                }
        }
    }
    __syncthreads();
    #pragma unroll
    for (int tm=0;tm<4;tm++) {
        int r0 = wm + tm*16 + (lane >> 2);
        float inv0 = 1.f/lrow[r0];
        float inv1 = 1.f/lrow[r0+8];
        #pragma unroll
        for (int tn=0;tn<2;tn++) {
            int cd = wd + tn*8 + (lane & 3)*2;
            size_t base0 = ((size_t)b*Sc + q0 + r0)*Ec + h*HDc + cd;
            float v0 = o[tm][tn][0]*inv0, v1 = o[tm][tn][1]*inv0;
            float v2 = o[tm][tn][2]*inv1, v3 = o[tm][tn][3]*inv1;
            __nv_bfloat16 h0 = __float2bfloat16(v0), h1 = __float2bfloat16(v1);
            __nv_bfloat16 h2 = __float2bfloat16(v2), h3 = __float2bfloat16(v3);
            __nv_bfloat16 l0 = __float2bfloat16(v0 - __bfloat162float(h0));
            __nv_bfloat16 l1 = __float2bfloat16(v1 - __bfloat162float(h1));
            __nv_bfloat16 l2 = __float2bfloat16(v2 - __bfloat162float(h2));
            __nv_bfloat16 l3 = __float2bfloat16(v3 - __bfloat162float(h3));
            *(__nv_bfloat162*)(OgH + base0)        = __halves2bfloat162(h0, h1);
            *(__nv_bfloat162*)(OgH + base0 + 8*Ec) = __halves2bfloat162(h2, h3);
            *(__nv_bfloat162*)(OgL + base0)        = __halves2bfloat162(l0, l1);
            *(__nv_bfloat162*)(OgL + base0 + 8*Ec) = __halves2bfloat162(l2, l3);
        }
    }
}

// ---------------- residual + layernorm (vectorized, optional split out) ----
__global__ __launch_bounds__(256) void addln_k(const float* __restrict__ X,
                                               const float* __restrict__ Y,
                                               const float* __restrict__ g,
                                               const float* __restrict__ bb,
                                               float* __restrict__ out,
                                               __nv_bfloat16* __restrict__ outH,
                                               __nv_bfloat16* __restrict__ outL) {
    int row = blockIdx.x;
    size_t base = (size_t)row*Ec;
    int tid = threadIdx.x;
    float4 xv = *(const float4*)(X + base + tid*4);
    float4 yv = *(const float4*)(Y + base + tid*4);
    float t0 = xv.x + yv.x, t1 = xv.y + yv.y, t2 = xv.z + yv.z, t3 = xv.w + yv.w;
    double s  = (double)t0 + (double)t1 + (double)t2 + (double)t3;
    double sq = (double)t0*t0 + (double)t1*t1 + (double)t2*t2 + (double)t3*t3;
    #pragma unroll
    for (int off = 16; off > 0; off >>= 1) {
        s  += __shfl_xor_sync(0xffffffffu, s,  off);
        sq += __shfl_xor_sync(0xffffffffu, sq, off);
    }
    __shared__ double ws_[8], wq_[8];
    __shared__ float s_mu, s_inv;
    int wid = tid >> 5, lane = tid & 31;
    if (lane == 0) { ws_[wid] = s; wq_[wid] = sq; }
    __syncthreads();
    if (tid == 0) {
        double S = 0.0, Q = 0.0;
        #pragma unroll
        for (int i = 0; i < 8; i++) { S += ws_[i]; Q += wq_[i]; }
        double mean = S/(double)Ec;
        double var  = Q/(double)Ec - mean*mean;
        s_mu  = (float)mean;
        s_inv = (float)(1.0/sqrt(var + 1e-5));
    }
    __syncthreads();
    float mu = s_mu, inv = s_inv;
    float4 gv = *(const float4*)(g  + tid*4);
    float4 bv = *(const float4*)(bb + tid*4);
    float r0 = (t0-mu)*inv*gv.x + bv.x;
    float r1 = (t1-mu)*inv*gv.y + bv.y;
    float r2 = (t2-mu)*inv*gv.z + bv.z;
    float r3 = (t3-mu)*inv*gv.w + bv.w;
    *(float4*)(out + base + tid*4) = make_float4(r0, r1, r2, r3);
    if (outH) {
        __nv_bfloat16 h0 = __float2bfloat16(r0), h1 = __float2bfloat16(r1);
        __nv_bfloat16 h2 = __float2bfloat16(r2), h3 = __float2bfloat16(r3);
        __nv_bfloat16 l0 = __float2bfloat16(r0 - __bfloat162float(h0));
        __nv_bfloat16 l1 = __float2bfloat16(r1 - __bfloat162float(h1));
        __nv_bfloat16 l2 = __float2bfloat16(r2 - __bfloat162float(h2));
        __nv_bfloat16 l3 = __float2bfloat16(r3 - __bfloat162float(h3));
        *(__nv_bfloat162*)(outH + base + tid*4)     = __halves2bfloat162(h0, h1);
        *(__nv_bfloat162*)(outH + base + tid*4 + 2) = __halves2bfloat162(h2, h3);
        *(__nv_bfloat162*)(outL + base + tid*4)     = __halves2bfloat162(l0, l1);
        *(__nv_bfloat162*)(outL + base + tid*4 + 2) = __halves2bfloat162(l2, l3);
    }
}

// ---------------- launcher ----------------
extern "C" void kernel_launch(void* const* d_in, const int* in_sizes, int n_in,
                              void* d_out, int out_size) {
    const float* x    = (const float*)d_in[0];
    const int*   mask = (const int*)  d_in[1];
    const float* Wq = (const float*)d_in[2];  const float* bq = (const float*)d_in[3];
    const float* Wk = (const float*)d_in[4];  const float* bk = (const float*)d_in[5];
    const float* Wv = (const float*)d_in[6];  const float* bv = (const float*)d_in[7];
    const float* Wo = (const float*)d_in[8];  const float* bo = (const float*)d_in[9];
    const float* W1 = (const float*)d_in[10]; const float* b1 = (const float*)d_in[11];
    const float* W2 = (const float*)d_in[12]; const float* b2 = (const float*)d_in[13];
    const float* g1 = (const float*)d_in[14]; const float* be1= (const float*)d_in[15];
    const float* g2 = (const float*)d_in[16]; const float* be2= (const float*)d_in[17];

    PP pp;
    pp.W[0]=Wq; pp.W[1]=Wk; pp.W[2]=Wv; pp.W[3]=Wo; pp.W[4]=W1; pp.W[5]=W2;
    pp.N[0]=Ec*Ec; pp.N[1]=Ec*Ec; pp.N[2]=Ec*Ec; pp.N[3]=Ec*Ec;
    pp.N[4]=DFFc*Ec; pp.N[5]=Ec*DFFc;

    const double spA[NM] = {0.25, 0.25, 0.25, 0.3/1.32, 0.375, 0.3125};
    const double spB[NM] = {0.94, 0.94, 0.94, 1.0-0.066, 0.96, 1.0-0.048};
    Ranks rk;
    for (int m=0;m<NM;m++) {
        double iA = spA[m]*(double)(pp.N[m]-1);
        rk.kA[m] = (long long)floor(iA);
        rk.fA[m] = iA - (double)rk.kA[m];
        double iB = spB[m]*(double)(pp.N[m]-1);
        rk.kB[m] = (long long)floor(iB);
        rk.fB[m] = iB - (double)rk.kB[m];
    }

    __nv_bfloat16 *pWhQKV,*pWlQKV,*pWhO,*pWlO,*pWh1,*pWl1,*pWh2,*pWl2;
    __nv_bfloat16 *pXh,*pXl,*pQKVh,*pQKVl,*pAttH,*pAttL,*pX1h,*pX1l,*pFFh,*pFFl;
    float *pBqkv,*pO,*pX1,*pF2;
    cudaGetSymbolAddress((void**)&pWhQKV, g_whQKV);
    cudaGetSymbolAddress((void**)&pWlQKV, g_wlQKV);
    cudaGetSymbolAddress((void**)&pWhO,   g_whO);
    cudaGetSymbolAddress((void**)&pWlO,   g_wlO);
    cudaGetSymbolAddress((void**)&pWh1,   g_wh1);
    cudaGetSymbolAddress((void**)&pWl1,   g_wl1);
    cudaGetSymbolAddress((void**)&pWh2,   g_wh2);
    cudaGetSymbolAddress((void**)&pWl2,   g_wl2);
    cudaGetSymbolAddress((void**)&pBqkv,  g_biasQKV);
    cudaGetSymbolAddress((void**)&pXh,    g_xh);
    cudaGetSymbolAddress((void**)&pXl,    g_xl);
    cudaGetSymbolAddress((void**)&pQKVh,  g_qkvh);
    cudaGetSymbolAddress((void**)&pQKVl,  g_qkvl);
    cudaGetSymbolAddress((void**)&pAttH,  g_atth);
    cudaGetSymbolAddress((void**)&pAttL,  g_attl);
    cudaGetSymbolAddress((void**)&pO,     g_oout);
    cudaGetSymbolAddress((void**)&pX1,    g_x1);
    cudaGetSymbolAddress((void**)&pX1h,   g_x1h);
    cudaGetSymbolAddress((void**)&pX1l,   g_x1l);
    cudaGetSymbolAddress((void**)&pFFh,   g_ffh);
    cudaGetSymbolAddress((void**)&pFFl,   g_ffl);
    cudaGetSymbolAddress((void**)&pF2,    g_f2);

    WSplit ws;
    ws.hi[0]=pWhQKV;         ws.lo[0]=pWlQKV;
    ws.hi[1]=pWhQKV+Ec*Ec;   ws.lo[1]=pWlQKV+Ec*Ec;
    ws.hi[2]=pWhQKV+2*Ec*Ec; ws.lo[2]=pWlQKV+2*Ec*Ec;
    ws.hi[3]=pWhO;           ws.lo[3]=pWlO;
    ws.hi[4]=pWh1;           ws.lo[4]=pWl1;
    ws.hi[5]=pWh2;           ws.lo[5]=pWl2;

    const dim3 hgrid(197, NM);   // ~8 CTAs/SM resident (was 148 -> 6/SM)

    // ---- weight preprocessing (scan fused into hist last block) ----
    init_k<<<128,256>>>(rk);
    hist_k<0,0><<<hgrid,256>>>(pp, rk);
    hist_k<0,1><<<hgrid,256>>>(pp, rk);
    hist_k<0,2><<<hgrid,256>>>(pp, rk);
    alpha_k<<<hgrid,256>>>(pp);
    hist_k<1,0><<<hgrid,256>>>(pp, rk);
    hist_k<1,1><<<hgrid,256>>>(pp, rk);
    hist_k<1,2><<<hgrid,256>>>(pp, rk);
    weff_k<<<hgrid,256>>>(pp, ws);
    concat_bias_k<<<(Ec+255)/256,256>>>(bq, bk, bv, pBqkv);
    split_k<<<(Mc*Ec/4+255)/256,256>>>((const float4*)x, pXh, pXl, Mc*Ec/4);

    // ---- tensor-core GEMM setup (2-stage: 80 KB, 2 CTAs/SM) ----
    size_t tc_smem = (size_t)8 * TILE_E * sizeof(__nv_bfloat16);
    cudaFuncSetAttribute(gemm_tc<0>, cudaFuncAttributeMaxDynamicSharedMemorySize, (int)tc_smem);
    cudaFuncSetAttribute(gemm_tc<2>, cudaFuncAttributeMaxDynamicSharedMemorySize, (int)tc_smem);
    cudaFuncSetAttribute(gemm_tc<3>, cudaFuncAttributeMaxDynamicSharedMemorySize, (int)tc_smem);

    // ---- fused QKV projection: route + split bf16 output ----
    gemm_tc<3><<<dim3(3*Ec/TBN, Mc/TBM),256,tc_smem>>>(
        pXh, pXl, pWhQKV, pWlQKV, pBqkv, nullptr, pQKVh, pQKVl, Mc, 3*Ec, Ec);

    // ---- attention (tensor core, split inputs) ----
    size_t at_smem = ATTN_SMEM_BYTES;
    cudaFuncSetAttribute(attn_tc, cudaFuncAttributeMaxDynamicSharedMemorySize, (int)at_smem);
    attn_tc<<<dim3(Sc/AQ, Hc, Bc), 256, at_smem>>>(pQKVh, pQKVl, mask, pAttH, pAttL);

    // ---- output projection + LN1 ----
    dim3 gEE(Ec/TBN, Mc/TBM);
    gemm_tc<0><<<gEE,256,tc_smem>>>(
        pAttH, pAttL, pWhO, pWlO, bo, pO, nullptr, nullptr, Mc, Ec, Ec);
    addln_k<<<Mc,256>>>(x, pO, g1, be1, pX1, pX1h, pX1l);

    // ---- FFN ----
    gemm_tc<2><<<dim3(DFFc/TBN, Mc/TBM),256,tc_smem>>>(
        pX1h, pX1l, pWh1, pWl1, b1, nullptr, pFFh, pFFl, Mc, DFFc, Ec);
    gemm_tc<0><<<gEE,256,tc_smem>>>(
        pFFh, pFFl, pWh2, pWl2, b2, pF2, nullptr, nullptr, Mc, Ec, DFFc);
    addln_k<<<Mc,256>>>(pX1, pF2, g2, be2, (float*)d_out, nullptr, nullptr);
}